// round 16
// baseline (speedup 1.0000x reference)
#include <cuda_runtime.h>
#include <math.h>

#define NN 1024
#define FD 512
#define TT 128
#define HH 512
#define W32 (NN/32)
#define GB  128            // persistent grid: <= 148 SMs, all co-resident
#define BT  512
#define MAXTGT NN

// dynamic smem layout (disjoint lifetimes aliased)
#define OFF_COLS 0          // ushort[32768]  (Phase D CSR)  / int[2048] scan (Phase B)
#define OFF_WA   65536      // float[1024] chain ping        / Phase E partials (8KB spans WA+WB)
#define OFF_WB   69632      // float[1024] chain pong
#define OFF_RS   73728      // float[1024] rowsum cache
#define OFF_RP   77824      // int[1025] rowptr cache        / float[1024] w (Phase E)
#define DYNBYTES 82176

// ---------------- device globals -------------------------------------------
// g_fwd/g_rev are convergent (atomicOr from identical inputs each call).
__device__ unsigned g_fwd[NN * W32];
__device__ unsigned g_rev[NN * W32];
__device__ int      g_rowptr[NN + 1];
__device__ float    g_rowsum[NN];
__device__ float    g_xln[NN * FD];
__device__ float    g_sab[TT];
__device__ float    g_somab[TT];
__device__ int      g_trow[MAXTGT];
__device__ int      g_tt[MAXTGT];
__device__ int      g_tcount;               // reset in Phase A every call
__device__ float    g_wvec[(size_t)MAXTGT * NN];
__device__ unsigned g_bar_cnt;
__device__ unsigned g_bar_gen;

// ---------------- grid barrier (cooperative-groups pattern) ------------------
// Fences execute in the MASTER THREAD ONLY. bar.sync gives block-internal
// happens-before into/out of the master; the master's single __threadfence()
// publishes the block's writes and invalidates this SM's L1. This is the
// documented CG grid.sync() implementation shape — the previous version ran
// __threadfence() in all 512 threads (2x per barrier), a ~400K-fence storm.
__device__ __forceinline__ void gbar() {
    __syncthreads();
    if (threadIdx.x == 0) {
        __threadfence();
        unsigned gen = *(volatile unsigned*)&g_bar_gen;
        if (atomicAdd(&g_bar_cnt, 1u) == GB - 1) {
            g_bar_cnt = 0;
            __threadfence();
            atomicExch(&g_bar_gen, gen + 1u);
        } else {
            while (*(volatile unsigned*)&g_bar_gen == gen) { }
        }
        __threadfence();
    }
    __syncthreads();
}

__device__ __forceinline__ float sgnf(float v) {
    return (v > 0.0f) ? 1.0f : ((v < 0.0f) ? -1.0f : 0.0f);
}

// ---------------- one persistent kernel, 3 grid barriers --------------------
__global__ void __launch_bounds__(BT) k_all(
    const float* __restrict__ x, const float* __restrict__ noise,
    const float* __restrict__ table, const int* __restrict__ src,
    const int* __restrict__ dst, const int* __restrict__ tn,
    float* __restrict__ out, int E)
{
    extern __shared__ char dyn[];
    __shared__ float s_red[32];
    __shared__ float s_wsum[4];

    const int bid = blockIdx.x, tid = threadIdx.x;
    const int g   = bid * BT + tid;

    // ===== Phase A: edges -> bitmaps + fp32 schedule + tcount reset =========
    if (g == 0) g_tcount = 0;
    for (int e = g; e < E; e += GB * BT) {
        int s = src[e], d = dst[e];
        atomicOr(&g_fwd[s * W32 + (d >> 5)], 1u << (d & 31));
        atomicOr(&g_rev[d * W32 + (s >> 5)], 1u << (s & 31));
    }
    if (bid == 0) {
        int lane = tid & 31, w = tid >> 5;
        float p = 0.0f;
        if (tid < TT) {
            float s = -6.0f + 12.0f * (float)tid * (1.0f / (float)(TT - 1));
            float beta = 1.0f / (1.0f + expf(-s)) * (0.02f - 1e-4f) + 1e-4f;
            p = log1pf(-beta);
            #pragma unroll
            for (int o = 1; o < 32; o <<= 1) {
                float v = __shfl_up_sync(0xffffffffu, p, o);
                if (lane >= o) p += v;
            }
            if (lane == 31) s_wsum[w] = p;
        }
        __syncthreads();
        if (tid < TT) {
            float base = 0.0f;
            #pragma unroll
            for (int ww = 0; ww < 4; ww++) if (ww < w) base += s_wsum[ww];
            float ab = expf(base + p);
            g_sab[tid]   = sqrtf(ab);
            g_somab[tid] = sqrtf(1.0f - ab);
        }
    }
    gbar();

    // ===== Phase B: scan(blk0) | rowsum+targets(blk1) | LN (all blocks) =====
    if (bid == 0) {
        int* a  = (int*)(dyn + OFF_COLS);
        int* b2 = a + NN;
        for (int i = tid; i < NN; i += BT) {
            int d = 0;
            const uint4* bp = (const uint4*)&g_rev[i * W32];
            #pragma unroll
            for (int q = 0; q < 8; q++) {
                uint4 v = bp[q];
                d += __popc(v.x) + __popc(v.y) + __popc(v.z) + __popc(v.w);
            }
            a[i] = d;
        }
        __syncthreads();
        for (int off = 1; off < NN; off <<= 1) {
            for (int i = tid; i < NN; i += BT)
                b2[i] = a[i] + ((i >= off) ? a[i - off] : 0);
            __syncthreads();
            int* t_ = a; a = b2; b2 = t_;
        }
        for (int i = tid; i < NN; i += BT) g_rowptr[i + 1] = a[i];
        if (tid == 0) g_rowptr[0] = 0;
        __syncthreads();
    } else if (bid == 1) {
        for (int i = tid; i < NN; i += BT) {
            int d = 0;
            const uint4* bp = (const uint4*)&g_fwd[i * W32];
            #pragma unroll
            for (int q = 0; q < 8; q++) {
                uint4 v = bp[q];
                d += __popc(v.x) + __popc(v.y) + __popc(v.z) + __popc(v.w);
            }
            g_rowsum[i] = (float)d * (1.0f / NN);
            int t = tn[i];
            if (t >= 1 && t <= 3) {
                int slot = atomicAdd(&g_tcount, 1);
                g_trow[slot] = i; g_tt[slot] = t;
            }
        }
    }
    {
        // LN / noise-shaping / base out / time embed: 8 rows per block
        int grp = tid >> 7, gt = tid & 127;
        int glane = gt & 31, gwp = gt >> 5;
        #pragma unroll
        for (int it = 0; it < 2; it++) {
            int row = bid * 8 + it * 4 + grp;
            const float4 xv = ((const float4*)(x + (size_t)row * FD))[gt];
            const float4 nv = ((const float4*)(noise + (size_t)row * FD))[gt];

            float sx = xv.x + xv.y + xv.z + xv.w;
            float sn = nv.x + nv.y + nv.z + nv.w;
            #pragma unroll
            for (int o = 16; o; o >>= 1) {
                sx += __shfl_down_sync(0xffffffffu, sx, o);
                sn += __shfl_down_sync(0xffffffffu, sn, o);
            }
            if (glane == 0) { s_red[grp * 4 + gwp] = sx; s_red[16 + grp * 4 + gwp] = sn; }
            __syncthreads();
            sx = s_red[grp*4+0] + s_red[grp*4+1] + s_red[grp*4+2] + s_red[grp*4+3];
            sn = s_red[16+grp*4+0] + s_red[16+grp*4+1] + s_red[16+grp*4+2] + s_red[16+grp*4+3];
            __syncthreads();
            float mux = sx * (1.0f / FD), mun = sn * (1.0f / FD);

            float4 xc = {xv.x-mux, xv.y-mux, xv.z-mux, xv.w-mux};
            float4 nc = {nv.x-mun, nv.y-mun, nv.z-mun, nv.w-mun};
            float vx = xc.x*xc.x + xc.y*xc.y + xc.z*xc.z + xc.w*xc.w;
            float vn = nc.x*nc.x + nc.y*nc.y + nc.z*nc.z + nc.w*nc.w;
            #pragma unroll
            for (int o = 16; o; o >>= 1) {
                vx += __shfl_down_sync(0xffffffffu, vx, o);
                vn += __shfl_down_sync(0xffffffffu, vn, o);
            }
            if (glane == 0) { s_red[grp * 4 + gwp] = vx; s_red[16 + grp * 4 + gwp] = vn; }
            __syncthreads();
            vx = s_red[grp*4+0] + s_red[grp*4+1] + s_red[grp*4+2] + s_red[grp*4+3];
            vn = s_red[16+grp*4+0] + s_red[16+grp*4+1] + s_red[16+grp*4+2] + s_red[16+grp*4+3];
            __syncthreads();

            float sxi = 1.0f / sqrtf(vx * (1.0f / FD) + 1e-5f);
            float sni = 1.4142135623730951f / sqrtf(vn * (1.0f / FD) + 1e-5f);

            float4 xl = {xc.x*sxi, xc.y*sxi, xc.z*sxi, xc.w*sxi};
            ((float4*)(g_xln + (size_t)row * FD))[gt] = xl;

            int tv = tn[row];
            float somab = g_somab[tv];
            float4 o;
            o.x = somab * sgnf(xl.x) * fabsf(nc.x * sni);
            o.y = somab * sgnf(xl.y) * fabsf(nc.y * sni);
            o.z = somab * sgnf(xl.z) * fabsf(nc.z * sni);
            o.w = somab * sgnf(xl.w) * fabsf(nc.w * sni);
            if (tv == 0) {
                float sab = g_sab[0];
                o.x += sab*xl.x; o.y += sab*xl.y; o.z += sab*xl.z; o.w += sab*xl.w;
            }
            ((float4*)(out + (size_t)row * FD))[gt] = o;

            const float4 te = ((const float4*)(table + (size_t)tv * HH))[gt];
            ((float4*)(out + (size_t)NN * FD + (size_t)row * HH))[gt] = te;
        }
    }
    gbar();
    const int ntgt = g_tcount;

    // ===== Phase D: per-target pull chain, ALL-SMEM inner loop ==============
    {
        unsigned short* scols = (unsigned short*)(dyn + OFF_COLS);
        float* swA = (float*)(dyn + OFF_WA);
        float* swB = (float*)(dyn + OFF_WB);
        float* srs = (float*)(dyn + OFF_RS);
        int*   srp = (int*)(dyn + OFF_RP);

        for (int ti = bid; ti < ntgt; ti += GB) {
            int r = g_trow[ti], t = g_tt[ti];
            int p = (t * (t + 1)) >> 1;          // 1, 3, or 6

            for (int i = tid; i <= NN; i += BT) srp[i] = g_rowptr[i];
            for (int i = tid; i < NN; i += BT)  srs[i] = g_rowsum[i];
            __syncthreads();

            // extract rev CSR cols into smem (bitmap -> scols), 2 rows/thread
            #pragma unroll
            for (int half = 0; half < 2; half++) {
                int i = tid + half * BT;
                int cpos = srp[i];
                const uint4* bp = (const uint4*)&g_rev[i * W32];
                #pragma unroll
                for (int q = 0; q < 8; q++) {
                    uint4 v = bp[q];
                    int base = q * 128;
                    unsigned b;
                    b = v.x; while (b) { scols[cpos++] = (unsigned short)(base +      (__ffs(b)-1)); b &= b-1; }
                    b = v.y; while (b) { scols[cpos++] = (unsigned short)(base + 32 + (__ffs(b)-1)); b &= b-1; }
                    b = v.z; while (b) { scols[cpos++] = (unsigned short)(base + 64 + (__ffs(b)-1)); b &= b-1; }
                    b = v.w; while (b) { scols[cpos++] = (unsigned short)(base + 96 + (__ffs(b)-1)); b &= b-1; }
                }
            }
            for (int i = tid; i < NN; i += BT) swA[i] = (i == r) ? 1.0f : 0.0f;
            __syncthreads();

            float* w  = swA;
            float* wn = swB;
            for (int a = 0; a < p; a++) {
                #pragma unroll
                for (int half = 0; half < 2; half++) {
                    int i = tid + half * BT;
                    int beg = srp[i], end = srp[i + 1];
                    float acc = 0.0f;
                    #pragma unroll 4
                    for (int e = beg; e < end; e++) acc += w[scols[e]];
                    wn[i] = acc * (1.0f / NN) - srs[i] * w[i];
                }
                __syncthreads();
                float* tmp = w; w = wn; wn = tmp;
            }
            for (int i = tid; i < NN; i += BT) g_wvec[(size_t)ti * NN + i] = w[i];
            __syncthreads();
        }
    }
    gbar();

    // ===== Phase E: contraction out[r, chunk] += sab[t] * (w^T X) ===========
    {
        float4* part = (float4*)(dyn + OFF_WA);      // 16 groups x 32 float4
        float*  sw   = (float*)(dyn + OFF_RP);       // w vector
        int ntask = ntgt * 4;
        for (int task = bid; task < ntask; task += GB) {
            int ti = task >> 2, ch = task & 3;
            int r = g_trow[ti];
            float coef = g_sab[g_tt[ti]];
            for (int i = tid; i < NN; i += BT) sw[i] = g_wvec[(size_t)ti * NN + i];
            __syncthreads();

            int jg = tid >> 5, lane = tid & 31;      // 16 row-groups x 32 float4 lanes
            const float4* X = (const float4*)g_xln;
            float4 a = {0,0,0,0};
            int j0 = jg * 64;
            #pragma unroll 8
            for (int j = j0; j < j0 + 64; j++) {
                float wj = sw[j];
                float4 v = X[(size_t)j * 128 + ch * 32 + lane];
                a.x += wj * v.x; a.y += wj * v.y; a.z += wj * v.z; a.w += wj * v.w;
            }
            part[jg * 32 + lane] = a;
            __syncthreads();
            if (tid < 32) {
                float4 s = {0,0,0,0};
                #pragma unroll
                for (int g2 = 0; g2 < 16; g2++) {
                    float4 v = part[g2 * 32 + tid];
                    s.x += v.x; s.y += v.y; s.z += v.z; s.w += v.w;
                }
                float4 o = ((float4*)(out + (size_t)r * FD + ch * 128))[tid];
                o.x += coef * s.x; o.y += coef * s.y;
                o.z += coef * s.z; o.w += coef * s.w;
                ((float4*)(out + (size_t)r * FD + ch * 128))[tid] = o;
            }
            __syncthreads();
        }
    }
}

// ---------------- orchestration: ONE launch ---------------------------------
extern "C" void kernel_launch(void* const* d_in, const int* in_sizes, int n_in,
                              void* d_out, int out_size) {
    const float* x     = (const float*)d_in[0];
    const float* noise = (const float*)d_in[1];
    const float* table = (const float*)d_in[2];
    const int*   src   = (const int*)d_in[3];
    const int*   dst   = (const int*)d_in[4];
    const int*   tn    = (const int*)d_in[5];
    int E = in_sizes[3];
    float* out = (float*)d_out;

    cudaFuncSetAttribute(k_all, cudaFuncAttributeMaxDynamicSharedMemorySize, DYNBYTES);
    k_all<<<GB, BT, DYNBYTES>>>(x, noise, table, src, dst, tn, out, E);
}